// round 1
// baseline (speedup 1.0000x reference)
#include <cuda_runtime.h>
#include <cstdint>

// Problem dims
#define NB    4096      // batch
#define IN_D  1024
#define NH0   4000
#define NH1   4000
#define NR    2000
#define NOUT  10

#define BASE_THRE 0.1f
#define R_M       3.0f
#define BETA      1.8f

__device__ __forceinline__ float sigm(float x) { return 1.0f / (1.0f + expf(-x)); }

// ----------------------------------------------------------------------------
// Tiled NT GEMM segment accumulator:
//   acc[8][8] += A[m0.., aoff + k] * B[n0.., k]   (A: row-major [M,lda], B: row-major [N,ldb], K-major dot)
// Block: 256 threads, tile 128x128, BK=16. Rows of B with n >= nmaxB contribute 0.
// ----------------------------------------------------------------------------
__device__ __forceinline__ void gemm_seg(
    const float* __restrict__ A, int lda, int aoff,
    const float* __restrict__ Bm, int ldb, int K, int nmaxB,
    int m0, int n0, float* As, float* Bs, float acc[8][8])
{
    const int tid = threadIdx.x;
    const int ar  = tid >> 2;          // 0..63
    const int ac  = (tid & 3) << 2;    // 0,4,8,12
    const int ty  = tid >> 4;          // 0..15
    const int tx  = tid & 15;          // 0..15

    for (int k0 = 0; k0 < K; k0 += 16) {
        // Load A tile 128x16 -> As[k][m]
        #pragma unroll
        for (int r = 0; r < 128; r += 64) {
            const float4 v = *(const float4*)(A + (size_t)(m0 + ar + r) * lda + (aoff + k0 + ac));
            As[(ac + 0) * 128 + ar + r] = v.x;
            As[(ac + 1) * 128 + ar + r] = v.y;
            As[(ac + 2) * 128 + ar + r] = v.z;
            As[(ac + 3) * 128 + ar + r] = v.w;
        }
        // Load B tile 128x16 -> Bs[k][n] (guard rows past nmaxB)
        #pragma unroll
        for (int r = 0; r < 128; r += 64) {
            const int n = n0 + ar + r;
            float4 v = make_float4(0.f, 0.f, 0.f, 0.f);
            if (n < nmaxB) v = *(const float4*)(Bm + (size_t)n * ldb + (k0 + ac));
            Bs[(ac + 0) * 128 + ar + r] = v.x;
            Bs[(ac + 1) * 128 + ar + r] = v.y;
            Bs[(ac + 2) * 128 + ar + r] = v.z;
            Bs[(ac + 3) * 128 + ar + r] = v.w;
        }
        __syncthreads();
        #pragma unroll
        for (int kk = 0; kk < 16; kk++) {
            float a[8], b[8];
            #pragma unroll
            for (int i = 0; i < 8; i++) a[i] = As[kk * 128 + ty * 8 + i];
            #pragma unroll
            for (int j = 0; j < 8; j++) b[j] = Bs[kk * 128 + tx * 8 + j];
            #pragma unroll
            for (int i = 0; i < 8; i++)
                #pragma unroll
                for (int j = 0; j < 8; j++)
                    acc[i][j] = fmaf(a[i], b[j], acc[i][j]);
        }
        __syncthreads();
    }
}

// ----------------------------------------------------------------------------
// Kernel 1: inp1 = x_t @ fc_w^T + fc_b, fused mem_update layer 1
//   grid: (ceil(NH0/128)=32, NB/128=32)
// ----------------------------------------------------------------------------
__global__ void __launch_bounds__(256, 2) gemm1_kernel(
    const float* __restrict__ x_t,  const float* __restrict__ fc_w, const float* __restrict__ fc_b,
    const float* __restrict__ mem1, const float* __restrict__ spk1, const float* __restrict__ b1,
    const float* __restrict__ tau_m1, const float* __restrict__ tau_adp1,
    float* __restrict__ out_mem1, float* __restrict__ out_spk1, float* __restrict__ out_b1)
{
    __shared__ float As[16 * 128];
    __shared__ float Bs[16 * 128];
    const int n0 = blockIdx.x * 128;
    const int m0 = blockIdx.y * 128;

    float acc[8][8];
    #pragma unroll
    for (int i = 0; i < 8; i++)
        #pragma unroll
        for (int j = 0; j < 8; j++) acc[i][j] = 0.f;

    gemm_seg(x_t, IN_D, 0, fc_w, IN_D, IN_D, NH0, m0, n0, As, Bs, acc);

    const int ty = threadIdx.x >> 4;
    const int tx = threadIdx.x & 15;

    float tmv[8], tav[8], fbv[8];
    #pragma unroll
    for (int j = 0; j < 8; j++) {
        const int n = n0 + tx * 8 + j;
        const bool v = (n < NH0);
        tmv[j] = sigm(v ? tau_m1[n]   : 0.f);
        tav[j] = sigm(v ? tau_adp1[n] : 0.f);
        fbv[j] = v ? fc_b[n] : 0.f;
    }
    #pragma unroll
    for (int i = 0; i < 8; i++) {
        const int m = m0 + ty * 8 + i;
        const size_t rowo = (size_t)m * NH0;
        #pragma unroll
        for (int j = 0; j < 8; j++) {
            const int n = n0 + tx * 8 + j;
            if (n >= NH0) continue;
            const size_t idx = rowo + n;
            const float sp = spk1[idx];
            const float bb = tav[j] * b1[idx] + (1.f - tav[j]) * sp;
            const float thre = BASE_THRE + BETA * bb;
            const float mem  = mem1[idx] * tmv[j]
                             + (1.f - tmv[j]) * R_M * (acc[i][j] + fbv[j])
                             - thre * sp;
            const float spn = (mem - thre) > 0.f ? 1.f : 0.f;
            out_mem1[idx] = mem;
            out_spk1[idx] = spn;
            out_b1[idx]   = bb;
        }
    }
}

// ----------------------------------------------------------------------------
// Kernel 2: input2hidden (both halves, segment-accumulated) + fused mem_update layer 2
//   grid: (ceil(NR/128)=16, NB/128=32, 2)   z=0 -> r_out (cols 0..1999), z=1 -> r_in (cols 2000..3999)
// ----------------------------------------------------------------------------
__global__ void __launch_bounds__(256, 2) gemm2_kernel(
    const float* __restrict__ spk1n, const float* __restrict__ spk2,
    const float* __restrict__ x2in_w,  const float* __restrict__ x2in_b,
    const float* __restrict__ rec4in_w, const float* __restrict__ rec4in_b,
    const float* __restrict__ in2out_w, const float* __restrict__ in2out_b,
    const float* __restrict__ rec4out_w, const float* __restrict__ rec4out_b,
    const float* __restrict__ out2in_w, const float* __restrict__ out2in_b,
    const float* __restrict__ mem2, const float* __restrict__ b2,
    const float* __restrict__ tau_m2, const float* __restrict__ tau_adp2,
    float* __restrict__ out_mem2, float* __restrict__ out_spk2, float* __restrict__ out_b2)
{
    __shared__ float As[16 * 128];
    __shared__ float Bs[16 * 128];
    const int n0   = blockIdx.x * 128;   // local column within the half
    const int m0   = blockIdx.y * 128;
    const int mode = blockIdx.z;         // 0 = r_out half, 1 = r_in half

    float acc[8][8];
    #pragma unroll
    for (int i = 0; i < 8; i++)
        #pragma unroll
        for (int j = 0; j < 8; j++) acc[i][j] = 0.f;

    if (mode == 0) {
        // r_out[n] = spk_out . rec4out_w[n] + spk_in . in2out_w[n]
        gemm_seg(spk2, NH1, 0,  rec4out_w, NR, NR, NR, m0, n0, As, Bs, acc);
        gemm_seg(spk2, NH1, NR, in2out_w,  NR, NR, NR, m0, n0, As, Bs, acc);
    } else {
        // r_in[n] = spk1n . x2in_w[n] + spk_out . out2in_w[n] + spk_in . rec4in_w[n]
        gemm_seg(spk1n, NH0, 0,  x2in_w,   NH0, NH0, NR, m0, n0, As, Bs, acc);
        gemm_seg(spk2,  NH1, 0,  out2in_w, NR,  NR,  NR, m0, n0, As, Bs, acc);
        gemm_seg(spk2,  NH1, NR, rec4in_w, NR,  NR,  NR, m0, n0, As, Bs, acc);
    }

    const int ty = threadIdx.x >> 4;
    const int tx = threadIdx.x & 15;

    float tmv[8], tav[8], biasv[8];
    #pragma unroll
    for (int j = 0; j < 8; j++) {
        const int n = n0 + tx * 8 + j;          // local col in half
        const bool v = (n < NR);
        const int g = mode * NR + (v ? n : 0);  // global col in H1
        tmv[j] = sigm(tau_m2[g]);
        tav[j] = sigm(tau_adp2[g]);
        float bias;
        if (mode == 0) bias = (v ? rec4out_b[n] + in2out_b[n] : 0.f);
        else           bias = (v ? x2in_b[n] + rec4in_b[n] + out2in_b[n] : 0.f);
        biasv[j] = bias;
    }
    #pragma unroll
    for (int i = 0; i < 8; i++) {
        const int m = m0 + ty * 8 + i;
        const size_t rowo = (size_t)m * NH1;
        #pragma unroll
        for (int j = 0; j < 8; j++) {
            const int n = n0 + tx * 8 + j;
            if (n >= NR) continue;
            const int g = mode * NR + n;
            const size_t idx = rowo + g;
            const float sp = spk2[idx];
            const float bb = tav[j] * b2[idx] + (1.f - tav[j]) * sp;
            const float thre = BASE_THRE + BETA * bb;
            const float mem  = mem2[idx] * tmv[j]
                             + (1.f - tmv[j]) * R_M * (acc[i][j] + biasv[j])
                             - thre * sp;
            const float spn = (mem - thre) > 0.f ? 1.f : 0.f;
            out_mem2[idx] = mem;
            out_spk2[idx] = spn;
            out_b2[idx]   = bb;
        }
    }
}

// ----------------------------------------------------------------------------
// Kernel 3: xo = spk2n[:, :2000] pooled (10 groups of 200) ; mem_out update ; log_softmax
//   grid: NB blocks, 320 threads (warp w handles group w)
// ----------------------------------------------------------------------------
__global__ void head_kernel(
    const float* __restrict__ spk2n, const float* __restrict__ mem_out,
    const float* __restrict__ out_tau_m,
    float* __restrict__ log_sm, float* __restrict__ mem_out_n)
{
    __shared__ float xo[NOUT];
    const int row  = blockIdx.x;
    const int w    = threadIdx.x >> 5;   // 0..9
    const int lane = threadIdx.x & 31;

    float s = 0.f;
    const float* p = spk2n + (size_t)row * NH1 + w * 200;
    for (int i = lane; i < 200; i += 32) s += p[i];
    #pragma unroll
    for (int o = 16; o > 0; o >>= 1) s += __shfl_down_sync(0xffffffffu, s, o);
    if (lane == 0) xo[w] = s;
    __syncthreads();

    if (threadIdx.x == 0) {
        float v[NOUT];
        float mx = -1e30f;
        #pragma unroll
        for (int o = 0; o < NOUT; o++) {
            const float m  = mem_out[(size_t)row * NOUT + o];
            const float sg = sigm(out_tau_m[o]);
            const float mo = m + (xo[o] - m) * sg;
            v[o] = mo;
            mem_out_n[(size_t)row * NOUT + o] = mo;
            mx = fmaxf(mx, mo);
        }
        float se = 0.f;
        #pragma unroll
        for (int o = 0; o < NOUT; o++) se += expf(v[o] - mx);
        const float lse = mx + logf(se);
        #pragma unroll
        for (int o = 0; o < NOUT; o++) log_sm[(size_t)row * NOUT + o] = v[o] - lse;
    }
}

// ----------------------------------------------------------------------------
// Launch
// ----------------------------------------------------------------------------
extern "C" void kernel_launch(void* const* d_in, const int* in_sizes, int n_in,
                              void* d_out, int out_size)
{
    const float* x_t       = (const float*)d_in[0];
    const float* mem1      = (const float*)d_in[1];
    const float* spk1      = (const float*)d_in[2];
    const float* b1        = (const float*)d_in[3];
    const float* mem2      = (const float*)d_in[4];
    const float* spk2      = (const float*)d_in[5];
    const float* b2        = (const float*)d_in[6];
    const float* mem_out   = (const float*)d_in[7];
    const float* fc_w      = (const float*)d_in[8];
    const float* fc_b      = (const float*)d_in[9];
    const float* tau_adp1  = (const float*)d_in[10];
    const float* tau_m1    = (const float*)d_in[11];
    const float* x2in_w    = (const float*)d_in[12];
    const float* x2in_b    = (const float*)d_in[13];
    const float* rec4in_w  = (const float*)d_in[14];
    const float* rec4in_b  = (const float*)d_in[15];
    const float* in2out_w  = (const float*)d_in[16];
    const float* in2out_b  = (const float*)d_in[17];
    const float* rec4out_w = (const float*)d_in[18];
    const float* rec4out_b = (const float*)d_in[19];
    const float* out2in_w  = (const float*)d_in[20];
    const float* out2in_b  = (const float*)d_in[21];
    const float* tau_adp2  = (const float*)d_in[22];
    const float* tau_m2    = (const float*)d_in[23];
    const float* out_tau_m = (const float*)d_in[24];

    float* out = (float*)d_out;
    const size_t BH = (size_t)NB * NH0;     // 16,384,000
    float* log_sm    = out;
    float* mem1n     = out + (size_t)NB * NOUT;
    float* spk1n     = mem1n + BH;
    float* b1n       = spk1n + BH;
    float* mem2n     = b1n   + BH;
    float* spk2n     = mem2n + BH;
    float* b2n       = spk2n + BH;
    float* mem_out_n = b2n   + BH;

    gemm1_kernel<<<dim3(32, 32), 256>>>(
        x_t, fc_w, fc_b, mem1, spk1, b1, tau_m1, tau_adp1,
        mem1n, spk1n, b1n);

    gemm2_kernel<<<dim3(16, 32, 2), 256>>>(
        spk1n, spk2,
        x2in_w, x2in_b, rec4in_w, rec4in_b, in2out_w, in2out_b,
        rec4out_w, rec4out_b, out2in_w, out2in_b,
        mem2, b2, tau_m2, tau_adp2,
        mem2n, spk2n, b2n);

    head_kernel<<<NB, 320>>>(spk2n, mem_out, out_tau_m, log_sm, mem_out_n);
}

// round 4
// speedup vs baseline: 1.7711x; 1.7711x over previous
#include <cuda_runtime.h>
#include <cuda_bf16.h>
#include <cstdint>

// Problem dims
#define NB    4096
#define IN_D  1024
#define NH0   4000
#define NH1   4000
#define NR    2000
#define NOUT  10
#define KP0   4096      // padded K, out-half  ([spk_out|pad][spk_in|pad])
#define KP1   8192      // padded K, in-half   (+ [spk1n|pad])
#define NPAD  2048

#define BASE_THRE 0.1f
#define R_M       3.0f
#define BETA      1.8f

// ---------------------------------------------------------------------------
// Static device scratch (zero-initialized; pad regions stay zero forever)
// ---------------------------------------------------------------------------
__device__ __align__(256) __nv_bfloat16 g_Wo[3][(size_t)NPAD * KP0];
__device__ __align__(256) __nv_bfloat16 g_Wi[3][(size_t)NPAD * KP1];
__device__ __align__(256) __nv_bfloat16 g_Acat[(size_t)NB * KP1];
__device__ float g_stm2[NH1];
__device__ float g_sta2[NH1];
__device__ float g_bias2[NH1];

__device__ __forceinline__ float sigm(float x) { return 1.0f / (1.0f + expf(-x)); }

__device__ __forceinline__ uint32_t smem_u32(const void* p) {
    uint32_t a;
    asm("{ .reg .u64 t; cvta.to.shared.u64 t, %1; cvt.u32.u64 %0, t; }" : "=r"(a) : "l"(p));
    return a;
}
__device__ __forceinline__ void cp16(uint32_t dst, const void* src) {
    asm volatile("cp.async.cg.shared.global [%0], [%1], 16;" :: "r"(dst), "l"(src) : "memory");
}
#define CP_COMMIT() asm volatile("cp.async.commit_group;" ::: "memory")
#define CP_WAIT1()  asm volatile("cp.async.wait_group 1;" ::: "memory")

__device__ __forceinline__ void ldm_x4(uint32_t& r0, uint32_t& r1, uint32_t& r2, uint32_t& r3,
                                       uint32_t addr) {
    asm volatile("ldmatrix.sync.aligned.m8n8.x4.shared.b16 {%0,%1,%2,%3}, [%4];"
                 : "=r"(r0), "=r"(r1), "=r"(r2), "=r"(r3) : "r"(addr));
}
__device__ __forceinline__ void mma16816(float* c, const uint32_t* a, uint32_t b0, uint32_t b1) {
    asm volatile(
        "mma.sync.aligned.m16n8k16.row.col.f32.bf16.bf16.f32 "
        "{%0,%1,%2,%3}, {%4,%5,%6,%7}, {%8,%9}, {%0,%1,%2,%3};"
        : "+f"(c[0]), "+f"(c[1]), "+f"(c[2]), "+f"(c[3])
        : "r"(a[0]), "r"(a[1]), "r"(a[2]), "r"(a[3]), "r"(b0), "r"(b1));
}

__device__ __forceinline__ void split3(float w, __nv_bfloat16& a, __nv_bfloat16& b,
                                       __nv_bfloat16& c) {
    a = __float2bfloat16(w);
    float r = w - __bfloat162float(a);
    b = __float2bfloat16(r);
    float r2 = r - __bfloat162float(b);
    c = __float2bfloat16(r2);
}

// ---------------------------------------------------------------------------
// Weight conversion: fp32 -> 3x bf16 planes, packed K layout; plus col params
// ---------------------------------------------------------------------------
__global__ void convW_kernel(
    const float* __restrict__ rec4out, const float* __restrict__ in2out,
    const float* __restrict__ out2in,  const float* __restrict__ rec4in,
    const float* __restrict__ x2in,
    const float* __restrict__ tau_m2,  const float* __restrict__ tau_adp2,
    const float* __restrict__ rec4out_b, const float* __restrict__ in2out_b,
    const float* __restrict__ out2in_b,  const float* __restrict__ rec4in_b,
    const float* __restrict__ x2in_b)
{
    const long S1 = (long)NR * NR;
    const long S2 = (long)NR * NH0;
    long i = (long)blockIdx.x * blockDim.x + threadIdx.x;
    if (i < 4 * S1) {
        int sel = (int)(i / S1);
        long r  = i % S1;
        int n = (int)(r / NR), k = (int)(r % NR);
        float w; size_t dst; int which;
        if (sel == 0)      { w = rec4out[r]; dst = (size_t)n * KP0 + k;        which = 0; }
        else if (sel == 1) { w = in2out[r];  dst = (size_t)n * KP0 + 2048 + k; which = 0; }
        else if (sel == 2) { w = out2in[r];  dst = (size_t)n * KP1 + k;        which = 1; }
        else               { w = rec4in[r];  dst = (size_t)n * KP1 + 2048 + k; which = 1; }
        __nv_bfloat16 a, b, c; split3(w, a, b, c);
        if (which == 0) { g_Wo[0][dst] = a; g_Wo[1][dst] = b; g_Wo[2][dst] = c; }
        else            { g_Wi[0][dst] = a; g_Wi[1][dst] = b; g_Wi[2][dst] = c; }
    } else if (i < 4 * S1 + S2) {
        long r = i - 4 * S1;
        int n = (int)(r / NH0), k = (int)(r % NH0);
        __nv_bfloat16 a, b, c; split3(x2in[r], a, b, c);
        size_t dst = (size_t)n * KP1 + 4096 + k;
        g_Wi[0][dst] = a; g_Wi[1][dst] = b; g_Wi[2][dst] = c;
    } else if (i < 4 * S1 + S2 + NH1) {
        int g = (int)(i - 4 * S1 - S2);
        g_stm2[g] = sigm(tau_m2[g]);
        g_sta2[g] = sigm(tau_adp2[g]);
        g_bias2[g] = (g < NR) ? (rec4out_b[g] + in2out_b[g])
                              : (x2in_b[g - NR] + rec4in_b[g - NR] + out2in_b[g - NR]);
    }
}

// Pack spikes (exact in bf16) into Acat: [spk_out|0][spk_in|0][spk1n|0]
__global__ void convA_kernel(const float* __restrict__ spk2, const float* __restrict__ spk1n)
{
    const long T1 = (long)NB * NH1;
    long i = (long)blockIdx.x * blockDim.x + threadIdx.x;
    if (i < T1) {
        int b = (int)(i / NH1), k = (int)(i % NH1);
        size_t dst = (size_t)b * KP1 + (k < NR ? k : k + 48);
        g_Acat[dst] = __float2bfloat16(spk2[i]);
    } else if (i < 2 * T1) {
        long r = i - T1;
        int b = (int)(r / NH0), k = (int)(r % NH0);
        g_Acat[(size_t)b * KP1 + 4096 + k] = __float2bfloat16(spk1n[r]);
    }
}

// ---------------------------------------------------------------------------
// GEMM2 via mma.sync bf16 (3-term split, DUAL accumulators), 128x128 tile,
// BK=32, cp.async 2-stage.  grid: (32, 16, 2)  block: 256 (8 warps, 2x4)
// acc0 accumulates term 0 (magnitude ~1); accS accumulates terms 1+2
// (magnitudes ~2^-9, 2^-18) -> rounding error of small terms stays ~2^-33 abs.
// ---------------------------------------------------------------------------
#define ROWB   80
#define TILEB  (128 * ROWB)          // 10240
#define STAGEB (4 * TILEB)           // 40960
#define SMEM_G2 (2 * STAGEB)         // 81920

__global__ void __launch_bounds__(256, 1) gemm2_mma_kernel(
    const float* __restrict__ spk2, const float* __restrict__ mem2,
    const float* __restrict__ b2,
    float* __restrict__ out_mem2, float* __restrict__ out_spk2, float* __restrict__ out_b2)
{
    extern __shared__ char smem[];
    const uint32_t sb = smem_u32(smem);
    const int tid  = threadIdx.x;
    const int wid  = tid >> 5;
    const int lane = tid & 31;
    const int mode = blockIdx.z;
    const int m0   = blockIdx.x * 128;
    const int n0   = blockIdx.y * 128;

    const int Kpad = mode ? KP1 : KP0;
    const int C    = Kpad / 32;
    const __nv_bfloat16* A0 = g_Acat + (size_t)m0 * KP1;
    const __nv_bfloat16* Wt[3];
    #pragma unroll
    for (int t = 0; t < 3; t++)
        Wt[t] = mode ? &g_Wi[t][(size_t)n0 * KP1] : &g_Wo[t][(size_t)n0 * KP0];

    const int row0 = tid >> 2;                   // 0..63
    const int ch0  = tid & 3;                    // 16B chunk in row

    auto issue = [&](int c, int s) {
        const size_t koff = (size_t)c * 32;      // bf16 elements
        #pragma unroll
        for (int j = 0; j < 2; j++) {
            const int row = row0 + j * 64;
            const uint32_t dofs = row * ROWB + ch0 * 16;
            cp16(sb + s * STAGEB + dofs, A0 + (size_t)row * KP1 + koff + ch0 * 8);
            #pragma unroll
            for (int t = 0; t < 3; t++)
                cp16(sb + s * STAGEB + (1 + t) * TILEB + dofs,
                     Wt[t] + (size_t)row * Kpad + koff + ch0 * 8);
        }
        CP_COMMIT();
    };

    const int wm = wid >> 2;     // 0..1
    const int wn = wid & 3;      // 0..3

    float acc0[4][4][4];
    float accS[4][4][4];
    #pragma unroll
    for (int mi = 0; mi < 4; mi++)
        #pragma unroll
        for (int ni = 0; ni < 4; ni++)
            #pragma unroll
            for (int r = 0; r < 4; r++) { acc0[mi][ni][r] = 0.f; accS[mi][ni][r] = 0.f; }

    const int lrow = lane & 15;
    const int lcol = (lane >> 4) * 16;

    issue(0, 0);
    issue(1, 1);

    for (int c = 0; c < C; c++) {
        const int s = c & 1;
        CP_WAIT1();
        __syncthreads();
        const uint32_t stb = sb + s * STAGEB;
        #pragma unroll
        for (int ks = 0; ks < 2; ks++) {
            uint32_t a[4][4];
            #pragma unroll
            for (int mi = 0; mi < 4; mi++) {
                const uint32_t ad = stb + (wm * 64 + mi * 16 + lrow) * ROWB + ks * 32 + lcol;
                ldm_x4(a[mi][0], a[mi][1], a[mi][2], a[mi][3], ad);
            }
            #pragma unroll
            for (int t = 0; t < 3; t++) {
                uint32_t b[4][2];
                #pragma unroll
                for (int nj = 0; nj < 2; nj++) {
                    uint32_t r0, r1, r2, r3;
                    const uint32_t bd = stb + (1 + t) * TILEB
                                      + (wn * 32 + nj * 16 + lrow) * ROWB + ks * 32 + lcol;
                    ldm_x4(r0, r1, r2, r3, bd);
                    b[nj * 2 + 0][0] = r0; b[nj * 2 + 0][1] = r2;
                    b[nj * 2 + 1][0] = r1; b[nj * 2 + 1][1] = r3;
                }
                float (*acc)[4][4] = (t == 0) ? acc0 : accS;
                #pragma unroll
                for (int mi = 0; mi < 4; mi++)
                    #pragma unroll
                    for (int ni = 0; ni < 4; ni++)
                        mma16816(acc[mi][ni], a[mi], b[ni][0], b[ni][1]);
            }
        }
        __syncthreads();
        if (c + 2 < C) issue(c + 2, s);
        else CP_COMMIT();     // keep group accounting consistent
    }

    // Epilogue: fused mem_update2 from accumulator registers
    const int erow = lane >> 2;            // 0..7
    const int ecol = (lane & 3) * 2;       // 0,2,4,6
    #pragma unroll
    for (int mi = 0; mi < 4; mi++) {
        #pragma unroll
        for (int r2i = 0; r2i < 2; r2i++) {
            const int m = m0 + wm * 64 + mi * 16 + erow + r2i * 8;
            const size_t rowo = (size_t)m * NH1;
            #pragma unroll
            for (int ni = 0; ni < 4; ni++) {
                #pragma unroll
                for (int cc = 0; cc < 2; cc++) {
                    const int nl = n0 + wn * 32 + ni * 8 + ecol + cc;
                    if (nl >= NR) continue;
                    const int g = mode * NR + nl;
                    const size_t idx = rowo + g;
                    const float v = (acc0[mi][ni][r2i * 2 + cc] + accS[mi][ni][r2i * 2 + cc])
                                  + g_bias2[g];
                    const float tm = g_stm2[g], ta = g_sta2[g];
                    const float sp = spk2[idx];
                    const float bb = ta * b2[idx] + (1.f - ta) * sp;
                    const float thre = BASE_THRE + BETA * bb;
                    const float mem = mem2[idx] * tm + (1.f - tm) * R_M * v - thre * sp;
                    out_mem2[idx] = mem;
                    out_spk2[idx] = (mem - thre) > 0.f ? 1.f : 0.f;
                    out_b2[idx]   = bb;
                }
            }
        }
    }
}

// ---------------------------------------------------------------------------
// GEMM1 (fp32 FFMA, at roofline) — unchanged
// ---------------------------------------------------------------------------
__device__ __forceinline__ void gemm_seg(
    const float* __restrict__ A, int lda, int aoff,
    const float* __restrict__ Bm, int ldb, int K, int nmaxB,
    int m0, int n0, float* As, float* Bs, float acc[8][8])
{
    const int tid = threadIdx.x;
    const int ar = tid >> 2, ac = (tid & 3) << 2;
    const int ty = tid >> 4, tx = tid & 15;
    for (int k0 = 0; k0 < K; k0 += 16) {
        #pragma unroll
        for (int r = 0; r < 128; r += 64) {
            const float4 v = *(const float4*)(A + (size_t)(m0 + ar + r) * lda + (aoff + k0 + ac));
            As[(ac + 0) * 128 + ar + r] = v.x; As[(ac + 1) * 128 + ar + r] = v.y;
            As[(ac + 2) * 128 + ar + r] = v.z; As[(ac + 3) * 128 + ar + r] = v.w;
        }
        #pragma unroll
        for (int r = 0; r < 128; r += 64) {
            const int n = n0 + ar + r;
            float4 v = make_float4(0.f, 0.f, 0.f, 0.f);
            if (n < nmaxB) v = *(const float4*)(Bm + (size_t)n * ldb + (k0 + ac));
            Bs[(ac + 0) * 128 + ar + r] = v.x; Bs[(ac + 1) * 128 + ar + r] = v.y;
            Bs[(ac + 2) * 128 + ar + r] = v.z; Bs[(ac + 3) * 128 + ar + r] = v.w;
        }
        __syncthreads();
        #pragma unroll
        for (int kk = 0; kk < 16; kk++) {
            float a[8], b[8];
            #pragma unroll
            for (int i = 0; i < 8; i++) a[i] = As[kk * 128 + ty * 8 + i];
            #pragma unroll
            for (int j = 0; j < 8; j++) b[j] = Bs[kk * 128 + tx * 8 + j];
            #pragma unroll
            for (int i = 0; i < 8; i++)
                #pragma unroll
                for (int j = 0; j < 8; j++) acc[i][j] = fmaf(a[i], b[j], acc[i][j]);
        }
        __syncthreads();
    }
}

__global__ void __launch_bounds__(256, 2) gemm1_kernel(
    const float* __restrict__ x_t, const float* __restrict__ fc_w, const float* __restrict__ fc_b,
    const float* __restrict__ mem1, const float* __restrict__ spk1, const float* __restrict__ b1,
    const float* __restrict__ tau_m1, const float* __restrict__ tau_adp1,
    float* __restrict__ out_mem1, float* __restrict__ out_spk1, float* __restrict__ out_b1)
{
    __shared__ float As[16 * 128];
    __shared__ float Bs[16 * 128];
    const int n0 = blockIdx.x * 128, m0 = blockIdx.y * 128;
    float acc[8][8];
    #pragma unroll
    for (int i = 0; i < 8; i++)
        #pragma unroll
        for (int j = 0; j < 8; j++) acc[i][j] = 0.f;
    gemm_seg(x_t, IN_D, 0, fc_w, IN_D, IN_D, NH0, m0, n0, As, Bs, acc);
    const int ty = threadIdx.x >> 4, tx = threadIdx.x & 15;
    float tmv[8], tav[8], fbv[8];
    #pragma unroll
    for (int j = 0; j < 8; j++) {
        const int n = n0 + tx * 8 + j; const bool v = (n < NH0);
        tmv[j] = sigm(v ? tau_m1[n] : 0.f);
        tav[j] = sigm(v ? tau_adp1[n] : 0.f);
        fbv[j] = v ? fc_b[n] : 0.f;
    }
    #pragma unroll
    for (int i = 0; i < 8; i++) {
        const int m = m0 + ty * 8 + i;
        const size_t rowo = (size_t)m * NH0;
        #pragma unroll
        for (int j = 0; j < 8; j++) {
            const int n = n0 + tx * 8 + j;
            if (n >= NH0) continue;
            const size_t idx = rowo + n;
            const float sp = spk1[idx];
            const float bb = tav[j] * b1[idx] + (1.f - tav[j]) * sp;
            const float thre = BASE_THRE + BETA * bb;
            const float mem = mem1[idx] * tmv[j] + (1.f - tmv[j]) * R_M * (acc[i][j] + fbv[j])
                            - thre * sp;
            out_mem1[idx] = mem;
            out_spk1[idx] = (mem - thre) > 0.f ? 1.f : 0.f;
            out_b1[idx]   = bb;
        }
    }
}

// ---------------------------------------------------------------------------
// Head: pooling + mem_out update + log_softmax
// ---------------------------------------------------------------------------
__global__ void head_kernel(
    const float* __restrict__ spk2n, const float* __restrict__ mem_out,
    const float* __restrict__ out_tau_m,
    float* __restrict__ log_sm, float* __restrict__ mem_out_n)
{
    __shared__ float xo[NOUT];
    const int row = blockIdx.x;
    const int w = threadIdx.x >> 5, lane = threadIdx.x & 31;
    float s = 0.f;
    const float* p = spk2n + (size_t)row * NH1 + w * 200;
    for (int i = lane; i < 200; i += 32) s += p[i];
    #pragma unroll
    for (int o = 16; o > 0; o >>= 1) s += __shfl_down_sync(0xffffffffu, s, o);
    if (lane == 0) xo[w] = s;
    __syncthreads();
    if (threadIdx.x == 0) {
        float v[NOUT];
        float mx = -1e30f;
        #pragma unroll
        for (int o = 0; o < NOUT; o++) {
            const float m = mem_out[(size_t)row * NOUT + o];
            const float mo = m + (xo[o] - m) * sigm(out_tau_m[o]);
            v[o] = mo; mem_out_n[(size_t)row * NOUT + o] = mo;
            mx = fmaxf(mx, mo);
        }
        float se = 0.f;
        #pragma unroll
        for (int o = 0; o < NOUT; o++) se += expf(v[o] - mx);
        const float lse = mx + logf(se);
        #pragma unroll
        for (int o = 0; o < NOUT; o++) log_sm[(size_t)row * NOUT + o] = v[o] - lse;
    }
}

// ---------------------------------------------------------------------------
// Launch
// ---------------------------------------------------------------------------
extern "C" void kernel_launch(void* const* d_in, const int* in_sizes, int n_in,
                              void* d_out, int out_size)
{
    const float* x_t       = (const float*)d_in[0];
    const float* mem1      = (const float*)d_in[1];
    const float* spk1      = (const float*)d_in[2];
    const float* b1        = (const float*)d_in[3];
    const float* mem2      = (const float*)d_in[4];
    const float* spk2      = (const float*)d_in[5];
    const float* b2        = (const float*)d_in[6];
    const float* mem_out   = (const float*)d_in[7];
    const float* fc_w      = (const float*)d_in[8];
    const float* fc_b      = (const float*)d_in[9];
    const float* tau_adp1  = (const float*)d_in[10];
    const float* tau_m1    = (const float*)d_in[11];
    const float* x2in_w    = (const float*)d_in[12];
    const float* x2in_b    = (const float*)d_in[13];
    const float* rec4in_w  = (const float*)d_in[14];
    const float* rec4in_b  = (const float*)d_in[15];
    const float* in2out_w  = (const float*)d_in[16];
    const float* in2out_b  = (const float*)d_in[17];
    const float* rec4out_w = (const float*)d_in[18];
    const float* rec4out_b = (const float*)d_in[19];
    const float* out2in_w  = (const float*)d_in[20];
    const float* out2in_b  = (const float*)d_in[21];
    const float* tau_adp2  = (const float*)d_in[22];
    const float* tau_m2    = (const float*)d_in[23];
    const float* out_tau_m = (const float*)d_in[24];

    float* out = (float*)d_out;
    const size_t BH = (size_t)NB * NH0;
    float* log_sm    = out;
    float* mem1n     = out + (size_t)NB * NOUT;
    float* spk1n     = mem1n + BH;
    float* b1n       = spk1n + BH;
    float* mem2n     = b1n + BH;
    float* spk2n     = mem2n + BH;
    float* b2n       = spk2n + BH;
    float* mem_out_n = b2n + BH;

    cudaFuncSetAttribute(gemm2_mma_kernel, cudaFuncAttributeMaxDynamicSharedMemorySize,
                         SMEM_G2);

    // weight split can start immediately (independent of gemm1)
    {
        const long T = 4L * NR * NR + (long)NR * NH0 + NH1;
        convW_kernel<<<(int)((T + 255) / 256), 256>>>(
            rec4out_w, in2out_w, out2in_w, rec4in_w, x2in_w,
            tau_m2, tau_adp2, rec4out_b, in2out_b, out2in_b, rec4in_b, x2in_b);
    }

    gemm1_kernel<<<dim3(32, 32), 256>>>(
        x_t, fc_w, fc_b, mem1, spk1, b1, tau_m1, tau_adp1, mem1n, spk1n, b1n);

    {
        const long T = 2L * NB * NH1;
        convA_kernel<<<(int)((T + 255) / 256), 256>>>(spk2, spk1n);
    }

    gemm2_mma_kernel<<<dim3(32, 16, 2), 256, SMEM_G2>>>(
        spk2, mem2, b2, mem2n, spk2n, b2n);

    head_kernel<<<NB, 320>>>(spk2n, mem_out, out_tau_m, log_sm, mem_out_n);
}